// round 9
// baseline (speedup 1.0000x reference)
#include <cuda_runtime.h>
#include <cuda_bf16.h>
#include <cstdint>

#define BATCH 2048
#define CAND  16
#define DIM   256
#define ADJW  96                    // 2*3*16
#define OUTW  (DIM + ADJW + 1)      // 353
#define THRED 0.8f
#define CHUNK 32                    // batches per k_neigh block

// ---- fused sim kernel geometry ----
#define NB     7                    // batches per block
#define SLOTS  (NB + 6)             // 13 batch tiles incl. +-3 halo
#define KC     128                  // K-chunk (2 chunks of DIM/2)
#define CPAD   136                  // bf16 chunk-row stride (68 words == 4 mod 32: ldsm clean)
#define FTHR   448                  // threads (14 warps)
#define NROWST (SLOTS * CAND)       // 208 tile rows

#define OFF_TILES  0
#define SZ_TILES   (NROWST * CPAD * 2)                  // 56576 B
#define OFF_RSUM   (OFF_TILES + SZ_TILES)
#define SZ_RSUM    (NB * 6 * CAND * 4)                  // 2688 B
#define OFF_INVS   (OFF_RSUM + SZ_RSUM)
#define SZ_INVS    (NB * CAND * 4)                      // 448 B
#define OFF_INVN   (OFF_INVS + SZ_INVS)
#define SZ_INVN    (NROWST * 4)                         // 832 B
#define OFF_NSQ    (OFF_INVN + SZ_INVN)
#define SZ_NSQ     (NROWST * 4)                         // 832 B
#define OFF_NMV    (OFF_NSQ + SZ_NSQ)
#define SZ_NMV     (NROWST * 4)                         // 832 B
#define SMEM_TOTAL (OFF_NMV + SZ_NMV)                   // 62208 B -> 3 CTAs/SM

#define FGRID ((BATCH + NB - 1) / NB)                   // 293 blocks

__device__ __forceinline__ uint32_t smem_u32(const void* p) {
    uint32_t a;
    asm("{ .reg .u64 t; cvta.to.shared.u64 t, %1; cvt.u32.u64 %0, t; }"
        : "=r"(a) : "l"(p));
    return a;
}

__device__ __forceinline__ void ldsm4(uint32_t addr, uint32_t& r0, uint32_t& r1,
                                      uint32_t& r2, uint32_t& r3) {
    asm volatile("ldmatrix.sync.aligned.m8n8.x4.shared.b16 {%0,%1,%2,%3}, [%4];"
                 : "=r"(r0), "=r"(r1), "=r"(r2), "=r"(r3) : "r"(addr));
}

__device__ __forceinline__ void mma16816(float* c, uint32_t a0, uint32_t a1,
                                         uint32_t a2, uint32_t a3,
                                         uint32_t b0, uint32_t b1) {
    asm volatile(
        "mma.sync.aligned.m16n8k16.row.col.f32.bf16.bf16.f32 "
        "{%0,%1,%2,%3}, {%4,%5,%6,%7}, {%8,%9}, {%0,%1,%2,%3};\n"
        : "+f"(c[0]), "+f"(c[1]), "+f"(c[2]), "+f"(c[3])
        : "r"(a0), "r"(a1), "r"(a2), "r"(a3), "r"(b0), "r"(b1));
}

// ---------------------------------------------------------------------------
// K_neigh: neighbor-mean (output cols [0,256)). Rolling 7-batch window.
// ---------------------------------------------------------------------------
__global__ __launch_bounds__(256) void k_neigh(const float* __restrict__ emb,
                                               const int* __restrict__ nm,
                                               float* __restrict__ out) {
    const int d4 = threadIdx.x;                       // 0..63
    const int c  = blockIdx.y * 4 + threadIdx.y;      // 0..15
    const int b0 = blockIdx.x * CHUNK;

    auto loadE = [&](int bb) -> float4 {
        if ((unsigned)bb < BATCH)
            return reinterpret_cast<const float4*>(emb)[((size_t)bb * CAND + c) * (DIM / 4) + d4];
        return make_float4(0.f, 0.f, 0.f, 0.f);
    };
    auto loadM = [&](int bb) -> float {
        if ((unsigned)bb < BATCH) return (float)nm[bb * CAND + c];
        return 0.f;
    };

    float4 w[7];
    float  m[6];
    #pragma unroll
    for (int i = 0; i < 7; i++) w[i] = loadE(b0 - 3 + i);
    #pragma unroll
    for (int i = 0; i < 6; i++) m[i] = loadM(b0 - 3 + i);

    #pragma unroll 8
    for (int s = 0; s < CHUNK; s++) {
        const int b = b0 + s;
        const float L1 = m[2], L2 = m[2] * m[1], L3 = m[2] * m[1] * m[0];
        const float R1 = m[3], R2 = m[3] * m[4], R3 = m[3] * m[4] * m[5];
        float4 acc;
        acc.x = (w[2].x*L1 + w[1].x*L2 + w[0].x*L3 + w[4].x*R1 + w[5].x*R2 + w[6].x*R3) * (1.f/6.f);
        acc.y = (w[2].y*L1 + w[1].y*L2 + w[0].y*L3 + w[4].y*R1 + w[5].y*R2 + w[6].y*R3) * (1.f/6.f);
        acc.z = (w[2].z*L1 + w[1].z*L2 + w[0].z*L3 + w[4].z*R1 + w[5].z*R2 + w[6].z*R3) * (1.f/6.f);
        acc.w = (w[2].w*L1 + w[1].w*L2 + w[0].w*L3 + w[4].w*R1 + w[5].w*R2 + w[6].w*R3) * (1.f/6.f);
        float* o = out + (size_t)(b * CAND + c) * OUTW + d4 * 4;
        o[0] = acc.x; o[1] = acc.y; o[2] = acc.z; o[3] = acc.w;
        #pragma unroll
        for (int i = 0; i < 6; i++) w[i] = w[i + 1];
        w[6] = loadE(b + 4);
        #pragma unroll
        for (int i = 0; i < 5; i++) m[i] = m[i + 1];
        m[5] = loadM(b + 3);
    }
}

// ---------------------------------------------------------------------------
// K_fused: band cosine adjacency (output cols [256,353)).
// K-chunked (2 chunks of 128): small smem -> 3 CTAs/SM. Norms accumulated in
// load phase (dot4 + shfl per row-chunk into nsq); raw bf16 tiles; ldmatrix
// fragment loads; accumulator MMAs across chunks.
// ---------------------------------------------------------------------------
__global__ __launch_bounds__(FTHR, 3) void k_fused(const float* __restrict__ emb,
                                                   const int* __restrict__ nm,
                                                   float* __restrict__ out) {
    extern __shared__ __align__(16) char smraw[];
    __nv_bfloat16* tiles = reinterpret_cast<__nv_bfloat16*>(smraw + OFF_TILES); // [208][136]
    float* rsum = reinterpret_cast<float*>(smraw + OFF_RSUM);                   // [NB][6][16]
    float* invs = reinterpret_cast<float*>(smraw + OFF_INVS);                   // [NB][16]
    float* invn = reinterpret_cast<float*>(smraw + OFF_INVN);                   // [208]
    float* nsq  = reinterpret_cast<float*>(smraw + OFF_NSQ);                    // [208]
    float* nmv  = reinterpret_cast<float*>(smraw + OFF_NMV);                    // [208]

    const int b0   = blockIdx.x * NB;
    const int t    = threadIdx.x;
    const int wid  = t >> 5;
    const int lane = t & 31;

    const int g  = lane >> 2;           // 0..7
    const int tg = lane & 3;            // 0..3
    const int jb = tg * 2;
    const uint32_t tiles_base = smem_u32(tiles);
    const int lmoff = (lane & 15) * CPAD + (lane >> 4) * 8;   // elements

    const int bi   = wid >> 1;          // 0..6
    const int cpb  = (wid & 1) * 3;     // 0 (left) or 3 (right)
    const int slot = bi + 3;
    int bslot[3];
    #pragma unroll
    for (int e = 0; e < 3; e++)
        bslot[e] = (cpb == 0) ? (slot - 1 - e) : (slot + 1 + e);

    float acc[3][8];
    #pragma unroll
    for (int e = 0; e < 3; e++)
        #pragma unroll
        for (int x = 0; x < 8; x++) acc[e][x] = 0.f;

    // ---- mask cache ----
    if (t < NROWST) {
        const int bb = b0 - 3 + (t >> 4);
        nmv[t] = ((unsigned)bb < BATCH) ? (float)nm[bb * CAND + (t & 15)] : 0.f;
    }

    // ================= two K-chunks =================
    #pragma unroll
    for (int cn = 0; cn < 2; cn++) {
        // ---- load chunk: warp handles rows wid+14i, groups of 3 for MLP ----
        #pragma unroll
        for (int grp = 0; grp < 5; grp++) {
            float4 v[3];
            int    rr[3];
            #pragma unroll
            for (int j = 0; j < 3; j++) {
                const int r = wid + 14 * (grp * 3 + j);
                rr[j] = r;
                float4 x = make_float4(0.f, 0.f, 0.f, 0.f);
                if (r < NROWST) {
                    const int bb = b0 - 3 + (r >> 4);
                    if ((unsigned)bb < BATCH)
                        x = *reinterpret_cast<const float4*>(
                            emb + ((size_t)bb * CAND + (r & 15)) * DIM + cn * KC + lane * 4);
                }
                v[j] = x;
            }
            #pragma unroll
            for (int j = 0; j < 3; j++) {
                if (rr[j] >= NROWST) continue;
                __nv_bfloat162 o0 = __floats2bfloat162_rn(v[j].x, v[j].y);
                __nv_bfloat162 o1 = __floats2bfloat162_rn(v[j].z, v[j].w);
                uint2 pk = *reinterpret_cast<uint2*>(&o0);
                (void)o1;
                pk.y = *reinterpret_cast<uint32_t*>(&o1);
                *reinterpret_cast<uint2*>(&tiles[rr[j] * CPAD + lane * 4]) = pk;
                float ss = v[j].x * v[j].x + v[j].y * v[j].y
                         + v[j].z * v[j].z + v[j].w * v[j].w;
                #pragma unroll
                for (int off = 16; off; off >>= 1)
                    ss += __shfl_xor_sync(0xffffffffu, ss, off);
                if (lane == 0) {
                    if (cn == 0) nsq[rr[j]] = ss;
                    else         nsq[rr[j]] += ss;
                }
            }
        }
        __syncthreads();   // tiles chunk + (cn==0: nmv) visible

        if (cn == 1 && t < NROWST)
            invn[t] = rsqrtf(fmaxf(nsq[t], 1e-12f));

        // ---- pair MMAs on this chunk: 8 kt steps ----
        uint32_t aad = tiles_base + (uint32_t)(slot * CAND * CPAD + lmoff) * 2;
        uint32_t bad0 = tiles_base + (uint32_t)(bslot[0] * CAND * CPAD + lmoff) * 2;
        uint32_t bad1 = tiles_base + (uint32_t)(bslot[1] * CAND * CPAD + lmoff) * 2;
        uint32_t bad2 = tiles_base + (uint32_t)(bslot[2] * CAND * CPAD + lmoff) * 2;
        #pragma unroll
        for (int kt = 0; kt < KC / 16; kt++) {
            uint32_t a0, a1, a2, a3;
            ldsm4(aad, a0, a1, a2, a3);
            aad += 32;
            uint32_t m0, m1, m2, m3;
            ldsm4(bad0, m0, m1, m2, m3);
            bad0 += 32;
            mma16816(acc[0],     a0, a1, a2, a3, m0, m2);
            mma16816(acc[0] + 4, a0, a1, a2, a3, m1, m3);
            ldsm4(bad1, m0, m1, m2, m3);
            bad1 += 32;
            mma16816(acc[1],     a0, a1, a2, a3, m0, m2);
            mma16816(acc[1] + 4, a0, a1, a2, a3, m1, m3);
            ldsm4(bad2, m0, m1, m2, m3);
            bad2 += 32;
            mma16816(acc[2],     a0, a1, a2, a3, m0, m2);
            mma16816(acc[2] + 4, a0, a1, a2, a3, m1, m3);
        }
        __syncthreads();   // chunk reads done (WAR before next load / epilogue)
    }

    // ---- gates from mask cache ----
    float gj[4][3];
    const int js[4] = {jb, jb + 1, jb + 8, jb + 9};
    #pragma unroll
    for (int jx = 0; jx < 4; jx++) {
        float a, b, c;
        if (cpb == 0) {         // left: masks of batches b-1, b-2, b-3
            a = nmv[(slot - 1) * CAND + js[jx]];
            b = nmv[(slot - 2) * CAND + js[jx]];
            c = nmv[(slot - 3) * CAND + js[jx]];
        } else {                // right: masks of batches b, b+1, b+2
            a = nmv[slot * CAND + js[jx]];
            b = nmv[(slot + 1) * CAND + js[jx]];
            c = nmv[(slot + 2) * CAND + js[jx]];
        }
        gj[jx][0] = a;
        gj[jx][1] = a * b;
        gj[jx][2] = a * b * c;
    }

    // ---- epilogue: cosine scale, threshold, gate, partial row sums ----
    const float inA0 = invn[slot * CAND + g];
    const float inA8 = invn[slot * CAND + g + 8];
    #pragma unroll
    for (int e = 0; e < 3; e++) {
        const int cp = cpb + e;
        const float* np = &invn[bslot[e] * CAND];
        const float ib0 = np[jb], ib1 = np[jb + 1], ib8 = np[jb + 8], ib9 = np[jb + 9];
        auto thr = [](float v, float ge) {
            v = (v > THRED) ? fminf(v, 1.f) : 0.f;
            return v * ge;
        };
        acc[e][0] = thr(acc[e][0] * inA0 * ib0, gj[0][e]);
        acc[e][1] = thr(acc[e][1] * inA0 * ib1, gj[1][e]);
        acc[e][2] = thr(acc[e][2] * inA8 * ib0, gj[0][e]);
        acc[e][3] = thr(acc[e][3] * inA8 * ib1, gj[1][e]);
        acc[e][4] = thr(acc[e][4] * inA0 * ib8, gj[2][e]);
        acc[e][5] = thr(acc[e][5] * inA0 * ib9, gj[3][e]);
        acc[e][6] = thr(acc[e][6] * inA8 * ib8, gj[2][e]);
        acc[e][7] = thr(acc[e][7] * inA8 * ib9, gj[3][e]);

        float sA = acc[e][0] + acc[e][1] + acc[e][4] + acc[e][5]; // row g
        float sB = acc[e][2] + acc[e][3] + acc[e][6] + acc[e][7]; // row g+8
        sA += __shfl_xor_sync(0xffffffffu, sA, 1);
        sA += __shfl_xor_sync(0xffffffffu, sA, 2);
        sB += __shfl_xor_sync(0xffffffffu, sB, 1);
        sB += __shfl_xor_sync(0xffffffffu, sB, 2);
        if (tg == 0) {
            rsum[(bi * 6 + cp) * CAND + g]     = sA;
            rsum[(bi * 6 + cp) * CAND + g + 8] = sB;
        }
    }
    __syncthreads();

    // ---- invs: per output row 1 / (L1 sum + ones col) ----
    if (t < NB * CAND) {
        const int tb = t >> 4, i = t & 15;
        float s = 1.0f;
        #pragma unroll
        for (int cp = 0; cp < 6; cp++) s += rsum[(tb * 6 + cp) * CAND + i];
        invs[t] = 1.0f / fmaxf(s, 1e-12f);
    }
    __syncthreads();

    // ---- normalized writes (guard partial last block) ----
    if (b0 + bi < BATCH) {
        const float ivA = invs[bi * CAND + g];
        const float ivB = invs[bi * CAND + g + 8];
        #pragma unroll
        for (int e = 0; e < 3; e++) {
            const int cp = cpb + e;
            float* oA = out + (size_t)((b0 + bi) * CAND + g)     * OUTW + DIM + cp * CAND + jb;
            float* oB = out + (size_t)((b0 + bi) * CAND + g + 8) * OUTW + DIM + cp * CAND + jb;
            oA[0] = acc[e][0] * ivA;  oA[1] = acc[e][1] * ivA;
            oA[8] = acc[e][4] * ivA;  oA[9] = acc[e][5] * ivA;
            oB[0] = acc[e][2] * ivB;  oB[1] = acc[e][3] * ivB;
            oB[8] = acc[e][6] * ivB;  oB[9] = acc[e][7] * ivB;
        }
    }
    if (t < NB * CAND && b0 + (t >> 4) < BATCH) {
        out[(size_t)(b0 * CAND + t) * OUTW + DIM + ADJW] = invs[t];  // ones column * inv
    }
}

// ---------------------------------------------------------------------------
extern "C" void kernel_launch(void* const* d_in, const int* in_sizes, int n_in,
                              void* d_out, int out_size) {
    (void)in_sizes; (void)n_in; (void)out_size;
    const float* emb = (const float*)d_in[0];
    const int*   nm  = (const int*)d_in[1];
    float*       out = (float*)d_out;

    (void)cudaFuncSetAttribute(k_fused, cudaFuncAttributeMaxDynamicSharedMemorySize,
                               SMEM_TOTAL);

    dim3 nb(64, 4);
    dim3 ng(BATCH / CHUNK, 4);
    k_neigh<<<ng, nb>>>(emb, nm, out);

    k_fused<<<FGRID, FTHR, SMEM_TOTAL>>>(emb, nm, out);
}